// round 11
// baseline (speedup 1.0000x reference)
#include <cuda_runtime.h>
#include <cuda_fp16.h>
#include <cstdint>

#define NN 2048
#define KA 64
#define ELLW 64
#define NITER 10
#define RPB 4   // rows per block in iter kernel

#define MSCALE 4194304.0f            // 2^22: lifts s~1e-7 into fp16 range
#define DESCALE (0.82f / 4194304.0f) // folded 0.82/MSCALE for epilogue

// ---------------- static device scratch (allocation-free contract) ----------
// Sentinel index NN points at zero pad rows/slots (device globals zero-init;
// pad rows never written, so they stay zero across graph replays).
__device__ unsigned short g_ell[2][NN * ELLW];
__device__ unsigned short g_ellT[ELLW / 4][NN][4];  // transposed+swizzled+sorted adj2
__device__ int    g_deg[2][NN];                      // padded degrees
__device__ float  g_Nn[2][(NN + 1) * KA];            // +1 zero pad row
__device__ float  g_P[2][NN * KA];
__device__ float2 g_qh[(size_t)NN * NN];             // {q, 0.18*Ht}
__device__ __half g_Mh[2][(size_t)(NN + 1) * NN];    // scaled fp16 M, +1 pad row

// 8B-granule bank swizzle: involution on low 4 bits, fixes sentinel 2048
__device__ __forceinline__ unsigned phi16(unsigned k) { return k ^ ((k >> 4) & 15u); }

// ---------------- packed f32x2 helpers --------------------------------------
__device__ __forceinline__ unsigned long long pk2(float lo, float hi) {
    unsigned long long r;
    asm("mov.b64 %0, {%1, %2};" : "=l"(r) : "f"(lo), "f"(hi));
    return r;
}
__device__ __forceinline__ void fma2(unsigned long long& d, unsigned long long a,
                                     unsigned long long b) {
    asm("fma.rn.f32x2 %0, %1, %2, %0;" : "+l"(d) : "l"(a), "l"(b));
}
__device__ __forceinline__ void upk2(unsigned long long v, float& lo, float& hi) {
    asm("mov.b64 {%0, %1}, %2;" : "=f"(lo), "=f"(hi) : "l"(v));
}

// ---------------- fused setup: ELL adjacency build + attr normalize ---------
__global__ void setup_kernel(const float* __restrict__ A1,
                             const float* __restrict__ A2,
                             const float* __restrict__ N1,
                             const float* __restrict__ N2) {
    int b = blockIdx.x;
    int warp = threadIdx.x >> 5;
    int lane = threadIdx.x & 31;
    if (b < 512) {
        int sel = b >> 8;
        int row = ((b & 255) << 3) + warp;
        const float* A = sel ? A2 : A1;
        const float* r = A + (size_t)row * NN;
        unsigned short* lst = &g_ell[sel][row * ELLW];
        lst[lane] = (unsigned short)NN;
        lst[lane + 32] = (unsigned short)NN;
        __syncwarp();
        int base = 0;
        for (int c0 = 0; c0 < NN; c0 += 32) {
            bool p = (r[c0 + lane] != 0.0f);
            unsigned m = __ballot_sync(0xffffffffu, p);
            if (p) {
                int pos = base + __popc(m & ((1u << lane) - 1u));
                if (pos < ELLW) lst[pos] = (unsigned short)(c0 + lane);
            }
            base += __popc(m);
        }
        __syncwarp();
        int d = (base < ELLW) ? base : ELLW;
        if (sel == 1 && lane == 0) {
            // Bank-conflict-aware ordering for iter stage 2 (8B granules, 16
            // bank groups): bucket by (phi16(v) - row) & 15, emit round-robin
            // so step p across consecutive rows hits distinct bank groups.
            unsigned short bkt[16][ELLW];
            int cnt[16];
            for (int g = 0; g < 16; g++) cnt[g] = 0;
            for (int p = 0; p < d; p++) {
                unsigned v = phi16((unsigned)lst[p]);
                int g = (int)((v - (unsigned)row) & 15u);
                bkt[g][cnt[g]++] = (unsigned short)v;
            }
            unsigned short tmp[ELLW];
            int n = 0;
            int ptr[16];
            for (int g = 0; g < 16; g++) ptr[g] = 0;
            while (n < d) {
                for (int g = 0; g < 16; g++)
                    if (ptr[g] < cnt[g]) tmp[n++] = bkt[g][ptr[g]++];
            }
            for (int p = d; p < ELLW; p++) tmp[p] = (unsigned short)NN;
            for (int p = 0; p < ELLW; p++)
                g_ellT[p >> 2][row][p & 3] = tmp[p];
        }
        if (lane == 0) {
            // padded degrees (pad harmless: sentinel rows/granule are zero)
            g_deg[sel][row] = (d + 3) & ~3;
        }
    } else {
        int idx = ((b - 512) << 3) + warp;  // 0..4095
        int sel = idx >> 11;
        int row = idx & 2047;
        const float* Nin = sel ? N2 : N1;
        size_t base = (size_t)row * KA;
        float a = Nin[base + lane];
        float c2 = Nin[base + 32 + lane];
        float ss = a * a + c2 * c2;
#pragma unroll
        for (int o = 16; o; o >>= 1) ss += __shfl_xor_sync(0xffffffffu, ss, o);
        float nrm = sqrtf(ss);
        float inv = (nrm > 0.0f) ? (1.0f / nrm) : 0.0f;
        g_Nn[sel][base + lane] = a * inv;
        g_Nn[sel][base + 32 + lane] = c2 * inv;
    }
}

// ---------------- P = A @ Nn (add-only SpMM over attrs) ---------------------
__global__ void spmm_attr_both() {
    int sel = blockIdx.x >> 11;
    int row = blockIdx.x & 2047;
    int lane = threadIdx.x;  // 64 threads = KA
    const unsigned short* lst = &g_ell[sel][row * ELLW];
    int deg = g_deg[sel][row];  // padded; sentinel rows are zero
    float acc = 0.0f;
    for (int p = 0; p < deg; p++)
        acc += g_Nn[sel][(size_t)lst[p] * KA + lane];
    g_P[sel][(size_t)row * KA + lane] = acc;
}

// ---------------- q = rsqrt(Nm*dm)*Nm; write {q, 0.18Ht} + fp16 M0 ---------
__global__ void __launch_bounds__(256) q_m0_kernel(const float* __restrict__ H) {
    __shared__ float sXT[64][68];  // [k][row]
    __shared__ float sYT[64][68];  // [k][col-row]
    int tx = threadIdx.x, ty = threadIdx.y;
    int t = ty * 16 + tx;
    int gi = blockIdx.y * 64, gj = blockIdx.x * 64;

    unsigned long long nm2[4][2], dm2[4][2];

    // ---- phase 1: Nm += N1n N2n^T ----
#pragma unroll
    for (int pass = 0; pass < 4; pass++) {
        int idx = pass * 256 + t;
        int row = idx >> 4;
        int k4 = (idx & 15) * 4;
        float4 a = *(const float4*)&g_Nn[0][(size_t)(gi + row) * KA + k4];
        float4 bvec = *(const float4*)&g_Nn[1][(size_t)(gj + row) * KA + k4];
        sXT[k4 + 0][row] = a.x; sXT[k4 + 1][row] = a.y;
        sXT[k4 + 2][row] = a.z; sXT[k4 + 3][row] = a.w;
        sYT[k4 + 0][row] = bvec.x; sYT[k4 + 1][row] = bvec.y;
        sYT[k4 + 2][row] = bvec.z; sYT[k4 + 3][row] = bvec.w;
    }
    __syncthreads();
#pragma unroll
    for (int r = 0; r < 4; r++) { nm2[r][0] = 0ull; nm2[r][1] = 0ull; }
#pragma unroll 4
    for (int k = 0; k < KA; k++) {
        float4 a = *(const float4*)&sXT[k][ty * 4];
        float4 bb = *(const float4*)&sYT[k][tx * 4];
        unsigned long long b01 = pk2(bb.x, bb.y), b23 = pk2(bb.z, bb.w);
        float av[4] = {a.x, a.y, a.z, a.w};
#pragma unroll
        for (int r = 0; r < 4; r++) {
            unsigned long long ad = pk2(av[r], av[r]);
            fma2(nm2[r][0], ad, b01);
            fma2(nm2[r][1], ad, b23);
        }
    }
    __syncthreads();

    // ---- phase 2: dm += P1 P2^T ----
#pragma unroll
    for (int pass = 0; pass < 4; pass++) {
        int idx = pass * 256 + t;
        int row = idx >> 4;
        int k4 = (idx & 15) * 4;
        float4 a = *(const float4*)&g_P[0][(size_t)(gi + row) * KA + k4];
        float4 bvec = *(const float4*)&g_P[1][(size_t)(gj + row) * KA + k4];
        sXT[k4 + 0][row] = a.x; sXT[k4 + 1][row] = a.y;
        sXT[k4 + 2][row] = a.z; sXT[k4 + 3][row] = a.w;
        sYT[k4 + 0][row] = bvec.x; sYT[k4 + 1][row] = bvec.y;
        sYT[k4 + 2][row] = bvec.z; sYT[k4 + 3][row] = bvec.w;
    }
    __syncthreads();
#pragma unroll
    for (int r = 0; r < 4; r++) { dm2[r][0] = 0ull; dm2[r][1] = 0ull; }
#pragma unroll 4
    for (int k = 0; k < KA; k++) {
        float4 a = *(const float4*)&sXT[k][ty * 4];
        float4 bb = *(const float4*)&sYT[k][tx * 4];
        unsigned long long b01 = pk2(bb.x, bb.y), b23 = pk2(bb.z, bb.w);
        float av[4] = {a.x, a.y, a.z, a.w};
#pragma unroll
        for (int r = 0; r < 4; r++) {
            unsigned long long ad = pk2(av[r], av[r]);
            fma2(dm2[r][0], ad, b01);
            fma2(dm2[r][1], ad, b23);
        }
    }
    __syncthreads();

    // ---- phase 3: H tile (transposed view) in sXT: sXT[j_loc][i_loc] ----
#pragma unroll
    for (int pass = 0; pass < 4; pass++) {
        int idx = pass * 256 + t;
        int jl = idx >> 4;
        int i4 = (idx & 15) * 4;
        float4 h = *(const float4*)&H[(size_t)(gj + jl) * NN + gi + i4];
        *(float4*)&sXT[jl][i4] = h;
    }
    __syncthreads();

#pragma unroll
    for (int r = 0; r < 4; r++) {
        int i = gi + ty * 4 + r;
        size_t base = (size_t)i * NN + gj + tx * 4;
        float nm[4], dm[4];
        upk2(nm2[r][0], nm[0], nm[1]); upk2(nm2[r][1], nm[2], nm[3]);
        upk2(dm2[r][0], dm[0], dm[1]); upk2(dm2[r][1], dm[2], dm[3]);
        float q[4], m[4];
        float4 qh0, qh1;
#pragma unroll
        for (int c = 0; c < 4; c++) {
            float D = nm[c] * dm[c];
            float dd = (D > 0.0f) ? (1.0f / sqrtf(D)) : 0.0f;
            q[c] = dd * nm[c];
            float ht = sXT[tx * 4 + c][ty * 4 + r];
            m[c] = q[c] * ht * MSCALE;  // M0 = q .* h, scaled
            if (c < 2) { ((float*)&qh0)[c * 2] = q[c]; ((float*)&qh0)[c * 2 + 1] = 0.18f * ht; }
            else       { ((float*)&qh1)[(c - 2) * 2] = q[c]; ((float*)&qh1)[(c - 2) * 2 + 1] = 0.18f * ht; }
        }
        *(float4*)&g_qh[base] = qh0;
        *(float4*)&g_qh[base + 2] = qh1;
        __half2 h01 = __floats2half2_rn(m[0], m[1]);
        __half2 h23 = __floats2half2_rn(m[2], m[3]);
        uint2 pk;
        pk.x = *(unsigned*)&h01;
        pk.y = *(unsigned*)&h23;
        *(uint2*)&g_Mh[0][base] = pk;
    }
}

// ---------------- fused iteration: S = A1 (q.*s) A2 ; s' ; M' ---------------
// (512,4): single wave at grid=512. M in scaled fp16; acc_s ALSO fp16 (8B
// granule per k = 4 halves r0..r3) -> stage-2 LDS.64 + HADD2 accumulation.
__global__ void __launch_bounds__(512, 4) iter_kernel(int par,
                                                      float* __restrict__ sOut,
                                                      int writeS, int writeM) {
    __shared__ __half acc_s[(NN + 1) * RPB];  // 16 KB; granule phi16(k)
    const __half* __restrict__ Min = g_Mh[par];
    __half* __restrict__ Mout = g_Mh[par ^ 1];
    int i0 = blockIdx.x * RPB;
    int tid = threadIdx.x;

    // stage 1: acc[k][r] = sum_{p in adj1(i0+r)} M[p][k]; 4-wide fp16 gathers
    // (uint2 = 4 halves), fp32 accumulate, fp16 swizzled scalar STS.
    const uint2* __restrict__ Min2 = (const uint2*)Min;
#pragma unroll
    for (int r = 0; r < RPB; r++) {
        float4 acc = make_float4(0.f, 0.f, 0.f, 0.f);
        const unsigned short* lst = &g_ell[0][(i0 + r) * ELLW];
        int pd = g_deg[0][i0 + r];  // pre-padded to multiple of 4
        for (int p = 0; p < pd; p += 4) {
            ushort4 rr = *(const ushort4*)(lst + p);  // uniform -> broadcast
            uint2 u0 = Min2[(size_t)rr.x * (NN / 4) + tid];
            uint2 u1 = Min2[(size_t)rr.y * (NN / 4) + tid];
            uint2 u2 = Min2[(size_t)rr.z * (NN / 4) + tid];
            uint2 u3 = Min2[(size_t)rr.w * (NN / 4) + tid];
#pragma unroll
            for (int s = 0; s < 4; s++) {
                uint2 u = (s == 0) ? u0 : (s == 1) ? u1 : (s == 2) ? u2 : u3;
                float2 f0 = __half22float2(*(__half2*)&u.x);
                float2 f1 = __half22float2(*(__half2*)&u.y);
                acc.x += f0.x; acc.y += f0.y; acc.z += f1.x; acc.w += f1.y;
            }
        }
        float vv[4] = {acc.x, acc.y, acc.z, acc.w};
#pragma unroll
        for (int c = 0; c < 4; c++)
            acc_s[phi16(tid * 4 + c) * RPB + r] = __float2half_rn(vv[c]);
    }
    if (tid == 0) {  // sentinel granule
        acc_s[NN * RPB + 0] = __ushort_as_half((unsigned short)0);
        acc_s[NN * RPB + 1] = __ushort_as_half((unsigned short)0);
        acc_s[NN * RPB + 2] = __ushort_as_half((unsigned short)0);
        acc_s[NN * RPB + 3] = __ushort_as_half((unsigned short)0);
    }
    __syncthreads();

    // stage 2: per column j, gather adj2 (pre-phi16-swizzled, conflict-sorted,
    // transposed lists). LDS.64 per gather; HADD2 into 8 half2 accumulators.
    const uint2* __restrict__ acc2 = (const uint2*)acc_s;
#pragma unroll
    for (int m = 0; m < NN / 512; m++) {
        int j = tid + m * 512;
        int pd = g_deg[1][j];  // pre-padded to multiple of 4
        int pgmax = __reduce_max_sync(0xffffffffu, pd) >> 2;
        __half2 z = __float2half2_rn(0.0f);
        __half2 A0 = z, A1 = z, B0 = z, B1 = z, C0 = z, C1 = z, D0 = z, D1 = z;
        for (int pg = 0; pg < pgmax; pg++) {
            ushort4 ii = *(const ushort4*)g_ellT[pg][j];  // coalesced
            uint2 u0 = acc2[ii.x];
            uint2 u1 = acc2[ii.y];
            uint2 u2 = acc2[ii.z];
            uint2 u3 = acc2[ii.w];
            A0 = __hadd2(A0, *(__half2*)&u0.x); A1 = __hadd2(A1, *(__half2*)&u0.y);
            B0 = __hadd2(B0, *(__half2*)&u1.x); B1 = __hadd2(B1, *(__half2*)&u1.y);
            C0 = __hadd2(C0, *(__half2*)&u2.x); C1 = __hadd2(C1, *(__half2*)&u2.y);
            D0 = __hadd2(D0, *(__half2*)&u3.x); D1 = __hadd2(D1, *(__half2*)&u3.y);
        }
        float2 fa0 = __half22float2(A0), fa1 = __half22float2(A1);
        float2 fb0 = __half22float2(B0), fb1 = __half22float2(B1);
        float2 fc0 = __half22float2(C0), fc1 = __half22float2(C1);
        float2 fd0 = __half22float2(D0), fd1 = __half22float2(D1);
        float S[RPB] = {(fa0.x + fb0.x) + (fc0.x + fd0.x),
                        (fa0.y + fb0.y) + (fc0.y + fd0.y),
                        (fa1.x + fb1.x) + (fc1.x + fd1.x),
                        (fa1.y + fb1.y) + (fc1.y + fd1.y)};
#pragma unroll
        for (int r = 0; r < RPB; r++) {
            size_t idx = (size_t)(i0 + r) * NN + j;
            float2 qh = g_qh[idx];  // {q, 0.18*Ht}
            float sv = qh.y + DESCALE * (qh.x * S[r]);
            if (writeM) Mout[idx] = __float2half_rn(qh.x * sv * MSCALE);
            if (writeS) sOut[idx] = sv;
        }
    }
}

// ---------------- launch ----------------------------------------------------
extern "C" void kernel_launch(void* const* d_in, const int* in_sizes, int n_in,
                              void* d_out, int out_size) {
    const float* A1 = (const float*)d_in[0];
    const float* A2 = (const float*)d_in[1];
    const float* N1 = (const float*)d_in[2];
    const float* N2 = (const float*)d_in[3];
    const float* H  = (const float*)d_in[4];
    float* out = (float*)d_out;

    setup_kernel<<<1024, 256>>>(A1, A2, N1, N2);       // 1
    spmm_attr_both<<<4096, 64>>>();                    // 2
    q_m0_kernel<<<dim3(32, 32), dim3(16, 16)>>>(H);    // 3

    for (int it = 0; it < NITER; it++) {               // 4..13
        int last = (it == NITER - 1);
        iter_kernel<<<NN / RPB, 512>>>(it & 1, out, last, !last);
    }
}

// round 12
// speedup vs baseline: 1.3738x; 1.3738x over previous
#include <cuda_runtime.h>
#include <cuda_fp16.h>
#include <cstdint>

#define NN 2048
#define KA 64
#define ELLW 64
#define NITER 10
#define RPB 4   // rows per block in iter kernel

#define MSCALE 4194304.0f            // 2^22: lifts s~1e-7 into fp16 range
#define DESCALE (0.82f / 4194304.0f) // folded 0.82/MSCALE for epilogue

// ---------------- static device scratch (allocation-free contract) ----------
// Sentinel index NN points at zero pad rows/slots (device globals zero-init;
// pad rows never written, so they stay zero across graph replays).
__device__ unsigned short g_ell[2][NN * ELLW];
__device__ unsigned short g_ellT[ELLW / 4][NN][4];  // permuted+swizzled+sorted adj2
__device__ int    g_degr[2][NN];                     // raw degrees
__device__ int    g_deg1p[NN];                       // padded graph-1 degrees
__device__ int    g_deg2p[NN];                       // permuted padded graph-2 degrees
__device__ int    g_sorted[NN];                      // jp -> original column j
__device__ int    g_pos[NN];                         // original j -> jp
__device__ float  g_Nn[2][(NN + 1) * KA];            // +1 zero pad row
__device__ float  g_P[2][NN * KA];
__device__ float2 g_qh[(size_t)NN * NN];             // {q, 0.18*Ht}, permuted cols
__device__ __half g_Mh[2][(size_t)(NN + 1) * NN];    // scaled fp16 M, permuted cols

// bank-group swizzle for 16B granules: involution, keeps sentinel 2048 fixed
__device__ __forceinline__ unsigned phi(unsigned k) { return k ^ ((k >> 3) & 7u); }

// ---------------- packed f32x2 helpers --------------------------------------
__device__ __forceinline__ unsigned long long pk2(float lo, float hi) {
    unsigned long long r;
    asm("mov.b64 %0, {%1, %2};" : "=l"(r) : "f"(lo), "f"(hi));
    return r;
}
__device__ __forceinline__ void fma2(unsigned long long& d, unsigned long long a,
                                     unsigned long long b) {
    asm("fma.rn.f32x2 %0, %1, %2, %0;" : "+l"(d) : "l"(a), "l"(b));
}
__device__ __forceinline__ void upk2(unsigned long long v, float& lo, float& hi) {
    asm("mov.b64 {%0, %1}, %2;" : "=f"(lo), "=f"(hi) : "l"(v));
}

// ---------------- setup: ELL adjacency build + attr normalize ---------------
__global__ void setup_kernel(const float* __restrict__ A1,
                             const float* __restrict__ A2,
                             const float* __restrict__ N1,
                             const float* __restrict__ N2) {
    int b = blockIdx.x;
    int warp = threadIdx.x >> 5;
    int lane = threadIdx.x & 31;
    if (b < 512) {
        int sel = b >> 8;
        int row = ((b & 255) << 3) + warp;
        const float* A = sel ? A2 : A1;
        const float* r = A + (size_t)row * NN;
        unsigned short* lst = &g_ell[sel][row * ELLW];
        lst[lane] = (unsigned short)NN;
        lst[lane + 32] = (unsigned short)NN;
        __syncwarp();
        int base = 0;
        for (int c0 = 0; c0 < NN; c0 += 32) {
            bool p = (r[c0 + lane] != 0.0f);
            unsigned m = __ballot_sync(0xffffffffu, p);
            if (p) {
                int pos = base + __popc(m & ((1u << lane) - 1u));
                if (pos < ELLW) lst[pos] = (unsigned short)(c0 + lane);
            }
            base += __popc(m);
        }
        if (lane == 0) {
            int d = (base < ELLW) ? base : ELLW;
            g_degr[sel][row] = d;
            if (sel == 0) g_deg1p[row] = (d + 3) & ~3;
        }
    } else {
        int idx = ((b - 512) << 3) + warp;  // 0..4095
        int sel = idx >> 11;
        int row = idx & 2047;
        const float* Nin = sel ? N2 : N1;
        size_t base = (size_t)row * KA;
        float a = Nin[base + lane];
        float c2 = Nin[base + 32 + lane];
        float ss = a * a + c2 * c2;
#pragma unroll
        for (int o = 16; o; o >>= 1) ss += __shfl_xor_sync(0xffffffffu, ss, o);
        float nrm = sqrtf(ss);
        float inv = (nrm > 0.0f) ? (1.0f / nrm) : 0.0f;
        g_Nn[sel][base + lane] = a * inv;
        g_Nn[sel][base + 32 + lane] = c2 * inv;
    }
}

// ---------------- stable degree-rank of graph-2 columns ---------------------
// block j: rank = #{k : (d_k, k) < (d_j, j)} -> deterministic permutation.
__global__ void sort_kernel() {
    __shared__ int red[256];
    int j = blockIdx.x;
    int tid = threadIdx.x;
    int dj = g_degr[1][j];
    int cnt = 0;
    for (int k = tid; k < NN; k += 256) {
        int dk = g_degr[1][k];
        cnt += (dk < dj) || (dk == dj && k < j);
    }
    red[tid] = cnt;
    __syncthreads();
    for (int off = 128; off; off >>= 1) {
        if (tid < off) red[tid] += red[tid + off];
        __syncthreads();
    }
    if (tid == 0) {
        int rank = red[0];
        g_pos[j] = rank;
        g_sorted[rank] = j;
        g_deg2p[rank] = (dj + 3) & ~3;
    }
}

// ---------------- build permuted/swizzled/conflict-sorted adj2 lists --------
__global__ void ellT_kernel() {
    int jp = blockIdx.x * 8 + (threadIdx.x >> 5);
    if ((threadIdx.x & 31) != 0) return;
    int j = g_sorted[jp];
    int d = g_degr[1][j];
    const unsigned short* lst = &g_ell[1][j * ELLW];
    // bucket by relative 16B-granule bank group, emit round-robin
    unsigned short bkt[8][ELLW];
    int cnt[8] = {0, 0, 0, 0, 0, 0, 0, 0};
    for (int p = 0; p < d; p++) {
        unsigned pp = phi((unsigned)g_pos[lst[p]]);
        int g = (int)((pp - (unsigned)jp) & 7u);
        bkt[g][cnt[g]++] = (unsigned short)pp;
    }
    unsigned short tmp[ELLW];
    int n = 0;
    int ptr[8] = {0, 0, 0, 0, 0, 0, 0, 0};
    while (n < d) {
        for (int g = 0; g < 8; g++)
            if (ptr[g] < cnt[g]) tmp[n++] = bkt[g][ptr[g]++];
    }
    for (int p = d; p < ELLW; p++) tmp[p] = (unsigned short)NN;
    for (int p = 0; p < ELLW; p++)
        g_ellT[p >> 2][jp][p & 3] = tmp[p];
}

// ---------------- P = A @ Nn (add-only SpMM over attrs) ---------------------
__global__ void spmm_attr_both() {
    int sel = blockIdx.x >> 11;
    int row = blockIdx.x & 2047;
    int lane = threadIdx.x;  // 64 threads = KA
    const unsigned short* lst = &g_ell[sel][row * ELLW];
    int deg = g_degr[sel][row];
    float acc = 0.0f;
    for (int p = 0; p < deg; p++)
        acc += g_Nn[sel][(size_t)lst[p] * KA + lane];
    g_P[sel][(size_t)row * KA + lane] = acc;
}

// ---------------- q = rsqrt(Nm*dm)*Nm; {q, 0.18Ht} + fp16 M0 ----------------
// Column side (graph-2) runs in PERMUTED space via g_sorted.
__global__ void __launch_bounds__(256) q_m0_kernel(const float* __restrict__ H) {
    __shared__ float sXT[64][68];  // [k][row]
    __shared__ float sYT[64][68];  // [k][col-row]
    int tx = threadIdx.x, ty = threadIdx.y;
    int t = ty * 16 + tx;
    int gi = blockIdx.y * 64, gj = blockIdx.x * 64;

    unsigned long long nm2[4][2], dm2[4][2];

    // ---- phase 1: Nm += N1n N2n^T (cols permuted) ----
#pragma unroll
    for (int pass = 0; pass < 4; pass++) {
        int idx = pass * 256 + t;
        int row = idx >> 4;
        int k4 = (idx & 15) * 4;
        int oj = g_sorted[gj + row];
        float4 a = *(const float4*)&g_Nn[0][(size_t)(gi + row) * KA + k4];
        float4 bvec = *(const float4*)&g_Nn[1][(size_t)oj * KA + k4];
        sXT[k4 + 0][row] = a.x; sXT[k4 + 1][row] = a.y;
        sXT[k4 + 2][row] = a.z; sXT[k4 + 3][row] = a.w;
        sYT[k4 + 0][row] = bvec.x; sYT[k4 + 1][row] = bvec.y;
        sYT[k4 + 2][row] = bvec.z; sYT[k4 + 3][row] = bvec.w;
    }
    __syncthreads();
#pragma unroll
    for (int r = 0; r < 4; r++) { nm2[r][0] = 0ull; nm2[r][1] = 0ull; }
#pragma unroll 4
    for (int k = 0; k < KA; k++) {
        float4 a = *(const float4*)&sXT[k][ty * 4];
        float4 bb = *(const float4*)&sYT[k][tx * 4];
        unsigned long long b01 = pk2(bb.x, bb.y), b23 = pk2(bb.z, bb.w);
        float av[4] = {a.x, a.y, a.z, a.w};
#pragma unroll
        for (int r = 0; r < 4; r++) {
            unsigned long long ad = pk2(av[r], av[r]);
            fma2(nm2[r][0], ad, b01);
            fma2(nm2[r][1], ad, b23);
        }
    }
    __syncthreads();

    // ---- phase 2: dm += P1 P2^T (cols permuted) ----
#pragma unroll
    for (int pass = 0; pass < 4; pass++) {
        int idx = pass * 256 + t;
        int row = idx >> 4;
        int k4 = (idx & 15) * 4;
        int oj = g_sorted[gj + row];
        float4 a = *(const float4*)&g_P[0][(size_t)(gi + row) * KA + k4];
        float4 bvec = *(const float4*)&g_P[1][(size_t)oj * KA + k4];
        sXT[k4 + 0][row] = a.x; sXT[k4 + 1][row] = a.y;
        sXT[k4 + 2][row] = a.z; sXT[k4 + 3][row] = a.w;
        sYT[k4 + 0][row] = bvec.x; sYT[k4 + 1][row] = bvec.y;
        sYT[k4 + 2][row] = bvec.z; sYT[k4 + 3][row] = bvec.w;
    }
    __syncthreads();
#pragma unroll
    for (int r = 0; r < 4; r++) { dm2[r][0] = 0ull; dm2[r][1] = 0ull; }
#pragma unroll 4
    for (int k = 0; k < KA; k++) {
        float4 a = *(const float4*)&sXT[k][ty * 4];
        float4 bb = *(const float4*)&sYT[k][tx * 4];
        unsigned long long b01 = pk2(bb.x, bb.y), b23 = pk2(bb.z, bb.w);
        float av[4] = {a.x, a.y, a.z, a.w};
#pragma unroll
        for (int r = 0; r < 4; r++) {
            unsigned long long ad = pk2(av[r], av[r]);
            fma2(dm2[r][0], ad, b01);
            fma2(dm2[r][1], ad, b23);
        }
    }
    __syncthreads();

    // ---- phase 3: H tile (transposed, permuted rows of H) ----
#pragma unroll
    for (int pass = 0; pass < 4; pass++) {
        int idx = pass * 256 + t;
        int jl = idx >> 4;
        int i4 = (idx & 15) * 4;
        float4 h = *(const float4*)&H[(size_t)g_sorted[gj + jl] * NN + gi + i4];
        *(float4*)&sXT[jl][i4] = h;
    }
    __syncthreads();

#pragma unroll
    for (int r = 0; r < 4; r++) {
        int i = gi + ty * 4 + r;
        size_t base = (size_t)i * NN + gj + tx * 4;
        float nm[4], dm[4];
        upk2(nm2[r][0], nm[0], nm[1]); upk2(nm2[r][1], nm[2], nm[3]);
        upk2(dm2[r][0], dm[0], dm[1]); upk2(dm2[r][1], dm[2], dm[3]);
        float q[4], m[4];
        float4 qh0, qh1;
#pragma unroll
        for (int c = 0; c < 4; c++) {
            float D = nm[c] * dm[c];
            float dd = (D > 0.0f) ? (1.0f / sqrtf(D)) : 0.0f;
            q[c] = dd * nm[c];
            float ht = sXT[tx * 4 + c][ty * 4 + r];
            m[c] = q[c] * ht * MSCALE;  // M0 = q .* h, scaled
            if (c < 2) { ((float*)&qh0)[c * 2] = q[c]; ((float*)&qh0)[c * 2 + 1] = 0.18f * ht; }
            else       { ((float*)&qh1)[(c - 2) * 2] = q[c]; ((float*)&qh1)[(c - 2) * 2 + 1] = 0.18f * ht; }
        }
        *(float4*)&g_qh[base] = qh0;
        *(float4*)&g_qh[base + 2] = qh1;
        __half2 h01 = __floats2half2_rn(m[0], m[1]);
        __half2 h23 = __floats2half2_rn(m[2], m[3]);
        uint2 pk;
        pk.x = *(unsigned*)&h01;
        pk.y = *(unsigned*)&h23;
        *(uint2*)&g_Mh[0][base] = pk;
    }
}

// ---------------- fused iteration: S = A1 (q.*s) A2 ; s' ; M' ---------------
// (512,4): single wave at grid=512. M fp16 (halved gather traffic), acc fp32.
// Columns degree-sorted => warp-uniform stage-2 trip counts.
__global__ void __launch_bounds__(512, 4) iter_kernel(int par,
                                                      float* __restrict__ sOut,
                                                      int writeS, int writeM) {
    __shared__ float acc_s[(NN + 1) * RPB];  // granule phi(k) holds [k][r0..3]
    const __half* __restrict__ Min = g_Mh[par];
    __half* __restrict__ Mout = g_Mh[par ^ 1];
    int i0 = blockIdx.x * RPB;
    int tid = threadIdx.x;

    // stage 1: acc[k][r] = sum_{p in adj1(i0+r)} M[p][k]; 4-wide fp16 gathers
    // (uint2 = 4 halves), fp32 accumulate, swizzled scalar STS.
    const uint2* __restrict__ Min2 = (const uint2*)Min;
#pragma unroll
    for (int r = 0; r < RPB; r++) {
        float4 acc = make_float4(0.f, 0.f, 0.f, 0.f);
        const unsigned short* lst = &g_ell[0][(i0 + r) * ELLW];
        int pd = g_deg1p[i0 + r];  // pre-padded to multiple of 4
        for (int p = 0; p < pd; p += 4) {
            ushort4 rr = *(const ushort4*)(lst + p);  // uniform -> broadcast
            uint2 u0 = Min2[(size_t)rr.x * (NN / 4) + tid];
            uint2 u1 = Min2[(size_t)rr.y * (NN / 4) + tid];
            uint2 u2 = Min2[(size_t)rr.z * (NN / 4) + tid];
            uint2 u3 = Min2[(size_t)rr.w * (NN / 4) + tid];
#pragma unroll
            for (int s = 0; s < 4; s++) {
                uint2 u = (s == 0) ? u0 : (s == 1) ? u1 : (s == 2) ? u2 : u3;
                float2 f0 = __half22float2(*(__half2*)&u.x);
                float2 f1 = __half22float2(*(__half2*)&u.y);
                acc.x += f0.x; acc.y += f0.y; acc.z += f1.x; acc.w += f1.y;
            }
        }
        float vv[4] = {acc.x, acc.y, acc.z, acc.w};
#pragma unroll
        for (int c = 0; c < 4; c++)
            acc_s[phi(tid * 4 + c) * RPB + r] = vv[c];
    }
    if (tid == 0) {  // sentinel granule
        acc_s[NN * RPB + 0] = 0.f; acc_s[NN * RPB + 1] = 0.f;
        acc_s[NN * RPB + 2] = 0.f; acc_s[NN * RPB + 3] = 0.f;
    }
    __syncthreads();

    // stage 2: per permuted column jp, gather adj2 (pre-swizzled,
    // conflict-sorted, degree-uniform per warp); 4 indices / ushort4 load.
    const float4* __restrict__ acc4 = (const float4*)acc_s;
#pragma unroll
    for (int m = 0; m < NN / 512; m++) {
        int j = tid + m * 512;
        int pd = g_deg2p[j];  // pre-padded to multiple of 4
        int pgmax = __reduce_max_sync(0xffffffffu, pd) >> 2;
        float4 s0 = make_float4(0.f, 0.f, 0.f, 0.f);
        float4 s1 = make_float4(0.f, 0.f, 0.f, 0.f);
        for (int pg = 0; pg < pgmax; pg++) {
            ushort4 ii = *(const ushort4*)g_ellT[pg][j];  // coalesced
            float4 v0 = acc4[ii.x], v1 = acc4[ii.y];
            float4 v2 = acc4[ii.z], v3 = acc4[ii.w];
            s0.x += v0.x + v1.x; s0.y += v0.y + v1.y;
            s0.z += v0.z + v1.z; s0.w += v0.w + v1.w;
            s1.x += v2.x + v3.x; s1.y += v2.y + v3.y;
            s1.z += v2.z + v3.z; s1.w += v2.w + v3.w;
        }
        float S[RPB] = {s0.x + s1.x, s0.y + s1.y, s0.z + s1.z, s0.w + s1.w};
        int jorig = writeS ? g_sorted[j] : 0;
#pragma unroll
        for (int r = 0; r < RPB; r++) {
            size_t idx = (size_t)(i0 + r) * NN + j;
            float2 qh = g_qh[idx];  // {q, 0.18*Ht}
            float sv = qh.y + DESCALE * (qh.x * S[r]);
            if (writeM) Mout[idx] = __float2half_rn(qh.x * sv * MSCALE);
            if (writeS) sOut[(size_t)(i0 + r) * NN + jorig] = sv;
        }
    }
}

// ---------------- launch ----------------------------------------------------
extern "C" void kernel_launch(void* const* d_in, const int* in_sizes, int n_in,
                              void* d_out, int out_size) {
    const float* A1 = (const float*)d_in[0];
    const float* A2 = (const float*)d_in[1];
    const float* N1 = (const float*)d_in[2];
    const float* N2 = (const float*)d_in[3];
    const float* H  = (const float*)d_in[4];
    float* out = (float*)d_out;

    setup_kernel<<<1024, 256>>>(A1, A2, N1, N2);       // 1
    sort_kernel<<<NN, 256>>>();                        // 2
    ellT_kernel<<<NN / 8, 256>>>();                    // 3
    spmm_attr_both<<<4096, 64>>>();                    // 4
    q_m0_kernel<<<dim3(32, 32), dim3(16, 16)>>>(H);    // 5

    for (int it = 0; it < NITER; it++) {               // 6..15
        int last = (it == NITER - 1);
        iter_kernel<<<NN / RPB, 512>>>(it & 1, out, last, !last);
    }
}